// round 17
// baseline (speedup 1.0000x reference)
#include <cuda_runtime.h>
#include <cuda_fp16.h>
#include <cstdint>

using f16 = __half;

// Problem dims
constexpr int BATCH    = 8192;
constexpr int IN_SIZE  = 4096;
constexpr int HIDDEN   = 4096;
constexpr int OUT_SIZE = 1024;
constexpr int KDIM     = 4096;
constexpr int KT       = KDIM / 64;

// GEMM tiling: CTA 128x128, warp tile 64x32 (2x4), BK=64, 2 CTAs/SM
constexpr int TM = 128;
constexpr int TN = 128;
constexpr int BK = 64;
constexpr int STAGES = 3;
constexpr int ROW_ELEMS  = 72;
constexpr int A_ELEMS = TM * ROW_ELEMS;
constexpr int B_ELEMS = TN * ROW_ELEMS;
constexpr int STAGE_ELEMS = A_ELEMS + B_ELEMS;
constexpr int SMEM_BYTES = STAGES * STAGE_ELEMS * 2;  // 110592 -> 2 CTAs/SM

// fused grid layout (all spins reference strictly lower bid groups)
constexpr int NQ = 64;
constexpr int W1BASE = 0;                 // 64 blocks: quant w1 (64-row slices)
constexpr int XBASE  = NQ;                // 64 blocks: convert x (128-row slices)
constexpr int W2BASE = 2 * NQ;            // 64 blocks: quant w2
constexpr int W3BASE = 3 * NQ;            // 64 blocks: quant w3
constexpr int G1BASE = 4 * NQ;            // 2048 GEMM1
constexpr int G1 = (BATCH / TM) * (HIDDEN / TN);
constexpr int G2BASE = G1BASE + G1;       // 2048 GEMM2
constexpr int G2 = (BATCH / TM) * (HIDDEN / TN);
constexpr int G3BASE = G2BASE + G2;       // 512 GEMM3
constexpr int G3 = (BATCH / TM) * (OUT_SIZE / TN);
constexpr int GRID = G3BASE + G3;         // 4864

// ---------------- static device scratch ----------------
__device__ f16 g_w1s[HIDDEN * IN_SIZE];
__device__ f16 g_w2s[HIDDEN * HIDDEN];
__device__ f16 g_w3s[OUT_SIZE * HIDDEN];
__device__ f16 g_a[BATCH * IN_SIZE];
__device__ f16 g_b[BATCH * HIDDEN];
__device__ float g_part[3 * 2048];
__device__ uint32_t g_cnt_w1[32];   // per GEMM1 bn (2 slices each)
__device__ uint32_t g_cnt_x[64];    // per GEMM1 bm (1 slice each)
__device__ uint32_t g_cntW1all;
__device__ uint32_t g_cntW2;
__device__ uint32_t g_cntW3;
__device__ uint32_t g_cnt1[64];
__device__ uint32_t g_cnt2[64];

// ---------------- PTX helpers ----------------
__device__ __forceinline__ uint32_t sptr(const void* p) {
    return (uint32_t)__cvta_generic_to_shared(p);
}
__device__ __forceinline__ void cp16(const f16* dst_smem, const f16* src_gmem) {
    uint32_t d = sptr(dst_smem);
    asm volatile("cp.async.cg.shared.global [%0], [%1], 16;\n" :: "r"(d), "l"(src_gmem));
}
__device__ __forceinline__ void ldsm4(uint32_t* r, uint32_t addr) {
    asm volatile("ldmatrix.sync.aligned.m8n8.x4.shared.b16 {%0,%1,%2,%3}, [%4];"
                 : "=r"(r[0]), "=r"(r[1]), "=r"(r[2]), "=r"(r[3]) : "r"(addr));
}
__device__ __forceinline__ void mma_f16(float* d, const uint32_t* a, const uint32_t* b) {
    asm volatile(
        "mma.sync.aligned.m16n8k16.row.col.f32.f16.f16.f32 "
        "{%0,%1,%2,%3}, {%4,%5,%6,%7}, {%8,%9}, {%0,%1,%2,%3};"
        : "+f"(d[0]), "+f"(d[1]), "+f"(d[2]), "+f"(d[3])
        : "r"(a[0]), "r"(a[1]), "r"(a[2]), "r"(a[3]), "r"(b[0]), "r"(b[1]));
}
__device__ __forceinline__ void spin_ge(volatile uint32_t* p, uint32_t n) {
    while (*p < n) __nanosleep(200);
}

// ---------------- quant over contiguous float4 range (sign -> f16, partial |w| sum) ----------------
__device__ __forceinline__ void quant_range(const float4* __restrict__ w4,
                                            __half2* __restrict__ ws2,
                                            int base4, int cnt4, int layer,
                                            int partIdx, int tid) {
    float s = 0.f;
    for (int i = base4 + tid; i < base4 + cnt4; i += 256) {
        float4 v = w4[i];
        s += fabsf(v.x) + fabsf(v.y) + fabsf(v.z) + fabsf(v.w);
        f16 s0 = __float2half((v.x > 0.f) ? 1.f : ((v.x < 0.f) ? -1.f : 0.f));
        f16 s1 = __float2half((v.y > 0.f) ? 1.f : ((v.y < 0.f) ? -1.f : 0.f));
        f16 s2 = __float2half((v.z > 0.f) ? 1.f : ((v.z < 0.f) ? -1.f : 0.f));
        f16 s3 = __float2half((v.w > 0.f) ? 1.f : ((v.w < 0.f) ? -1.f : 0.f));
        ws2[2 * i]     = __halves2half2(s0, s1);
        ws2[2 * i + 1] = __halves2half2(s2, s3);
    }
    __shared__ float red[256];
    red[tid] = s;
    __syncthreads();
    for (int o = 128; o > 0; o >>= 1) {
        if (tid < o) red[tid] += red[tid + o];
        __syncthreads();
    }
    if (tid == 0) g_part[layer * 2048 + partIdx] = red[0];
}

// deterministic linear sum of 64 partials
__device__ __forceinline__ float sum64(const float* p) {
    float s = 0.f;
#pragma unroll 16
    for (int i = 0; i < 64; i++) s += __ldg(p + i);
    return s;
}

__global__ void init_kernel() {
    int t = threadIdx.x;
    if (t < 64) { g_cnt_x[t] = 0; g_cnt1[t] = 0; g_cnt2[t] = 0; }
    if (t < 32) g_cnt_w1[t] = 0;
    if (t == 0) { g_cntW1all = 0; g_cntW2 = 0; g_cntW3 = 0; }
}

// ---------------- GEMM body (128x128 CTA, 64x32 warp tiles) ----------------
__device__ __forceinline__ void gemm_body(
    const f16* __restrict__ A, const f16* __restrict__ Bs,
    const float* __restrict__ bias, const float* aPart, float invCnt,
    uint32_t* aSpin, uint32_t aNeed, int N, int bm, int bn,
    int epi, f16* __restrict__ oH, float* __restrict__ oF, f16* smem) {
    const int tid  = threadIdx.x;
    const int lane = tid & 31;
    const int warp = tid >> 5;
    const int wm = warp & 1;
    const int wn = warp >> 1;

    const f16* gA = A  + (size_t)bm * TM * KDIM;
    const f16* gB = Bs + (size_t)bn * TN * KDIM;

    const int crow = tid >> 3;
    const int ccol = (tid & 7) * 8;

    auto issue = [&](int kt, int stage) {
        f16* sa = smem + stage * STAGE_ELEMS;
        f16* sb = sa + A_ELEMS;
        const int kof = kt * BK;
#pragma unroll
        for (int rr = 0; rr < 4; rr++) {
            const int row = rr * 32 + crow;
            cp16(sa + row * ROW_ELEMS + ccol, gA + (size_t)row * KDIM + kof + ccol);
            cp16(sb + row * ROW_ELEMS + ccol, gB + (size_t)row * KDIM + kof + ccol);
        }
    };

    float acc[4][4][4];
#pragma unroll
    for (int i = 0; i < 4; i++)
#pragma unroll
        for (int j = 0; j < 4; j++)
#pragma unroll
            for (int v = 0; v < 4; v++) acc[i][j][v] = 0.f;

    const int a_off = (wm * 64 + (lane & 15)) * ROW_ELEMS + (lane >> 4) * 8;
    const int b_off = (wn * 32 + ((lane >> 4) & 1) * 8 + (lane & 7)) * ROW_ELEMS
                    + ((lane >> 3) & 1) * 8;

    issue(0, 0);
    asm volatile("cp.async.commit_group;" ::: "memory");
    issue(1, 1);
    asm volatile("cp.async.commit_group;" ::: "memory");

    for (int kt = 0; kt < KT; kt++) {
        const int stage = kt % STAGES;
        asm volatile("cp.async.wait_group 1;" ::: "memory");
        __syncthreads();
        const int kn = kt + 2;
        if (kn < KT) issue(kn, kn % STAGES);
        asm volatile("cp.async.commit_group;" ::: "memory");

        const f16* sA = smem + stage * STAGE_ELEMS;
        const f16* sB = sA + A_ELEMS;
#pragma unroll
        for (int ks = 0; ks < 4; ks++) {
            const int kc = ks * 16;
            uint32_t af[4][4], bf[4][2];
#pragma unroll
            for (int i = 0; i < 4; i++)
                ldsm4(af[i], sptr(sA + a_off + (i & 1) * 16 * ROW_ELEMS
                                     + (i >> 1) * 32 * ROW_ELEMS + kc));
#pragma unroll
            for (int jj = 0; jj < 2; jj++) {
                uint32_t r[4];
                ldsm4(r, sptr(sB + b_off + jj * 16 * ROW_ELEMS + kc));
                bf[2 * jj][0] = r[0]; bf[2 * jj][1] = r[1];
                bf[2 * jj + 1][0] = r[2]; bf[2 * jj + 1][1] = r[3];
            }
#pragma unroll
            for (int i = 0; i < 4; i++)
#pragma unroll
                for (int j = 0; j < 4; j++)
                    mma_f16(acc[i][j], af[i], bf[j]);
        }
    }

    // alpha: spin (long satisfied by now) + deterministic linear 64-sum
    if (tid == 0) spin_ge(aSpin, aNeed);
    __syncthreads();
    __threadfence();
    const float alpha = sum64(aPart) * invCnt;

    const int r0 = bm * TM + wm * 64 + (lane >> 2);
    const int c0 = bn * TN + wn * 32 + (lane & 3) * 2;
#pragma unroll
    for (int i = 0; i < 4; i++) {
#pragma unroll
        for (int j = 0; j < 4; j++) {
            int row = r0 + (i & 1) * 16 + (i >> 1) * 32;
            int col = c0 + j * 8;
            float bx = __ldg(bias + col), by = __ldg(bias + col + 1);
            float v00 = acc[i][j][0] * alpha + bx;
            float v01 = acc[i][j][1] * alpha + by;
            float v10 = acc[i][j][2] * alpha + bx;
            float v11 = acc[i][j][3] * alpha + by;
            if (epi == 0) {
                v00 = fmaxf(v00, 0.f); v01 = fmaxf(v01, 0.f);
                v10 = fmaxf(v10, 0.f); v11 = fmaxf(v11, 0.f);
                size_t i0 = (size_t)row * N + col;
                size_t i1 = (size_t)(row + 8) * N + col;
                *reinterpret_cast<__half2*>(oH + i0) =
                    __halves2half2(__float2half(v00), __float2half(v01));
                *reinterpret_cast<__half2*>(oH + i1) =
                    __halves2half2(__float2half(v10), __float2half(v11));
            } else {
                float2 s0, s1;
                s0.x = 1.f / (1.f + __expf(-v00));
                s0.y = 1.f / (1.f + __expf(-v01));
                s1.x = 1.f / (1.f + __expf(-v10));
                s1.y = 1.f / (1.f + __expf(-v11));
                *reinterpret_cast<float2*>(oF + (size_t)row * N + col)       = s0;
                *reinterpret_cast<float2*>(oF + (size_t)(row + 8) * N + col) = s1;
            }
        }
    }
}

// ---------------- fully fused kernel: all prep + all three GEMMs ----------------
__global__ void __launch_bounds__(256, 2) fused_kernel(
    const float4* __restrict__ xsrc,  const float4* __restrict__ w1src,
    const float4* __restrict__ w2src, const float4* __restrict__ w3src,
    const float* __restrict__ b1, const float* __restrict__ b2,
    const float* __restrict__ b3, float* __restrict__ dout) {
    extern __shared__ f16 smem[];
    const int bid = blockIdx.x;
    const int tid = threadIdx.x;

    if (bid < XBASE) {  // quant w1, 64-row slice q -> serves GEMM1 bn = q/2
        const int q = bid - W1BASE;
        const int cnt4 = HIDDEN * IN_SIZE / 4 / NQ;   // 65536 float4 = 64 rows
        quant_range(w1src, (__half2*)g_w1s, q * cnt4, cnt4, 0, q, tid);
        __threadfence();
        __syncthreads();
        if (tid == 0) {
            atomicAdd(&g_cnt_w1[q >> 1], 1u);
            atomicAdd(&g_cntW1all, 1u);
        }
        return;
    }
    if (bid < W2BASE) {  // convert x, 128-row slice c -> serves GEMM1 bm = c
        const int c = bid - XBASE;
        const int cnt4 = BATCH * IN_SIZE / 4 / NQ;    // 131072 float4 = 128 rows
        const int base4 = c * cnt4;
        __half2* xh = (__half2*)g_a;
        for (int i = base4 + tid; i < base4 + cnt4; i += 256) {
            float4 v = xsrc[i];
            xh[2 * i]     = __halves2half2(__float2half(v.x), __float2half(v.y));
            xh[2 * i + 1] = __halves2half2(__float2half(v.z), __float2half(v.w));
        }
        __threadfence();
        __syncthreads();
        if (tid == 0) atomicAdd(&g_cnt_x[c], 1u);
        return;
    }
    if (bid < W3BASE) {  // quant w2
        const int q = bid - W2BASE;
        const int cnt4 = HIDDEN * HIDDEN / 4 / NQ;
        quant_range(w2src, (__half2*)g_w2s, q * cnt4, cnt4, 1, q, tid);
        __threadfence();
        __syncthreads();
        if (tid == 0) atomicAdd(&g_cntW2, 1u);
        return;
    }
    if (bid < G1BASE) {  // quant w3
        const int q = bid - W3BASE;
        const int cnt4 = OUT_SIZE * HIDDEN / 4 / NQ;
        quant_range(w3src, (__half2*)g_w3s, q * cnt4, cnt4, 2, q, tid);
        __threadfence();
        __syncthreads();
        if (tid == 0) atomicAdd(&g_cntW3, 1u);
        return;
    }
    if (bid < G2BASE) {  // GEMM1: x @ w1s
        const int idx = bid - G1BASE;
        const int bn = idx & 31, bm = idx >> 5;
        if (tid == 0) {
            spin_ge(&g_cnt_x[bm], 1);
            spin_ge(&g_cnt_w1[bn], 2);
        }
        __syncthreads();
        __threadfence();
        gemm_body(g_a, g_w1s, b1, g_part,
                  1.0f / ((float)HIDDEN * (float)IN_SIZE),
                  &g_cntW1all, NQ, HIDDEN, bm, bn, 0, g_b, nullptr, smem);
        __threadfence();
        __syncthreads();
        if (tid == 0) atomicAdd(&g_cnt1[bm], 1u);
        return;
    }
    if (bid < G3BASE) {  // GEMM2: h1 @ w2s
        const int idx = bid - G2BASE;
        const int bn = idx & 31, bm = idx >> 5;
        if (tid == 0) {
            spin_ge(&g_cntW2, NQ);
            spin_ge(&g_cnt1[bm], 32);
        }
        __syncthreads();
        __threadfence();
        gemm_body(g_b, g_w2s, b2, g_part + 2048,
                  1.0f / ((float)HIDDEN * (float)HIDDEN),
                  &g_cntW2, NQ, HIDDEN, bm, bn, 0, g_a, nullptr, smem);
        __threadfence();
        __syncthreads();
        if (tid == 0) atomicAdd(&g_cnt2[bm], 1u);
        return;
    }
    {  // GEMM3: h2 @ w3s -> sigmoid f32
        const int idx = bid - G3BASE;
        const int bn = idx & 7, bm = idx >> 3;
        if (tid == 0) {
            spin_ge(&g_cntW3, NQ);
            spin_ge(&g_cnt2[bm], 32);
        }
        __syncthreads();
        __threadfence();
        gemm_body(g_a, g_w3s, b3, g_part + 4096,
                  1.0f / ((float)OUT_SIZE * (float)HIDDEN),
                  &g_cntW3, NQ, OUT_SIZE, bm, bn, 1, nullptr, dout, smem);
    }
}

// ---------------- host launch ----------------
extern "C" void kernel_launch(void* const* d_in, const int* in_sizes, int n_in,
                              void* d_out, int out_size) {
    const float* x  = (const float*)d_in[0];
    const float* w1 = (const float*)d_in[1];
    const float* b1 = (const float*)d_in[2];
    const float* w2 = (const float*)d_in[3];
    const float* b2 = (const float*)d_in[4];
    const float* w3 = (const float*)d_in[5];
    const float* b3 = (const float*)d_in[6];

    cudaFuncSetAttribute(fused_kernel, cudaFuncAttributeMaxDynamicSharedMemorySize, SMEM_BYTES);

    init_kernel<<<1, 256>>>();
    fused_kernel<<<GRID, 256, SMEM_BYTES>>>(
        (const float4*)x, (const float4*)w1, (const float4*)w2, (const float4*)w3,
        b1, b2, b3, (float*)d_out);
}